// round 1
// baseline (speedup 1.0000x reference)
#include <cuda_runtime.h>
#include <cuda_bf16.h>
#include <cstdint>

// GriddingDistance: trilinear scatter of two point clouds into 128^3 voxel
// grids per batch sample. out = [pred_grid (b*G), gt_grid (b*G)] fp32.
//
// R = 128, G = R^3, p = cloud*128 + 64 in [0, 128); 8 corner weights
// prod over axes of (d for +1 corner, 1-d for base), scatter-add.

#define GRID_R 128

__global__ __launch_bounds__(256)
void gridding_scatter_kernel(const float* __restrict__ pred,
                             const float* __restrict__ gt,
                             float* __restrict__ out,
                             int n_per_sample,
                             int total_points,
                             long long grid_per_cloud)
{
    int t = blockIdx.x * blockDim.x + threadIdx.x;
    if (t >= total_points) return;

    const float* __restrict__ pts = (blockIdx.y == 0) ? pred : gt;
    float* __restrict__ g = out + (long long)blockIdx.y * grid_per_cloud;

    // load point (3 consecutive floats)
    float px = fmaf(pts[3 * t + 0], 128.0f, 64.0f);
    float py = fmaf(pts[3 * t + 1], 128.0f, 64.0f);
    float pz = fmaf(pts[3 * t + 2], 128.0f, 64.0f);

    float fx = floorf(px), fy = floorf(py), fz = floorf(pz);
    float dx = px - fx,   dy = py - fy,   dz = pz - fz;

    int ix = (int)fx, iy = (int)fy, iz = (int)fz;

    // clip corners to [0, R-1] like the reference
    int ix0 = min(max(ix,     0), GRID_R - 1);
    int ix1 = min(max(ix + 1, 0), GRID_R - 1);
    int iy0 = min(max(iy,     0), GRID_R - 1);
    int iy1 = min(max(iy + 1, 0), GRID_R - 1);
    int iz0 = min(max(iz,     0), GRID_R - 1);
    int iz1 = min(max(iz + 1, 0), GRID_R - 1);

    float wx0 = 1.0f - dx, wx1 = dx;
    float wy0 = 1.0f - dy, wy1 = dy;
    float wz0 = 1.0f - dz, wz1 = dz;

    int sample = t / n_per_sample;
    long long base = (long long)sample * (GRID_R * GRID_R * GRID_R);
    float* __restrict__ gb = g + base;

    int rx0 = ix0 * GRID_R * GRID_R;
    int rx1 = ix1 * GRID_R * GRID_R;
    int ry0 = iy0 * GRID_R;
    int ry1 = iy1 * GRID_R;

    float w00 = wx0 * wy0;
    float w01 = wx0 * wy1;
    float w10 = wx1 * wy0;
    float w11 = wx1 * wy1;

    atomicAdd(gb + (rx0 + ry0 + iz0), w00 * wz0);
    atomicAdd(gb + (rx0 + ry0 + iz1), w00 * wz1);
    atomicAdd(gb + (rx0 + ry1 + iz0), w01 * wz0);
    atomicAdd(gb + (rx0 + ry1 + iz1), w01 * wz1);
    atomicAdd(gb + (rx1 + ry0 + iz0), w10 * wz0);
    atomicAdd(gb + (rx1 + ry0 + iz1), w10 * wz1);
    atomicAdd(gb + (rx1 + ry1 + iz0), w11 * wz0);
    atomicAdd(gb + (rx1 + ry1 + iz1), w11 * wz1);
}

extern "C" void kernel_launch(void* const* d_in, const int* in_sizes, int n_in,
                              void* d_out, int out_size)
{
    const float* pred = (const float*)d_in[0];
    const float* gt   = (const float*)d_in[1];
    float* out = (float*)d_out;

    const int G = GRID_R * GRID_R * GRID_R;            // 2097152
    int b = out_size / (2 * G);                        // 8
    int total_points = in_sizes[0] / 3;                // b * n = 524288
    int n = total_points / b;                          // 65536
    long long grid_per_cloud = (long long)b * G;       // 16777216

    // zero-init the poisoned output (graph-capturable async memset)
    cudaMemsetAsync(d_out, 0, (size_t)out_size * sizeof(float));

    dim3 grid((total_points + 255) / 256, 2);
    gridding_scatter_kernel<<<grid, 256>>>(pred, gt, out, n, total_points,
                                           grid_per_cloud);
}

// round 2
// speedup vs baseline: 1.1340x; 1.1340x over previous
#include <cuda_runtime.h>
#include <cuda_bf16.h>
#include <cstdint>

// GriddingDistance: trilinear scatter of two point clouds into 128^3 voxel
// grids per batch sample. out = [pred_grid (b*G), gt_grid (b*G)] fp32.
//
// Round 2: z-pair vectorized reductions. The two z-corners are contiguous;
// when iz0 is even they form an aligned 8B segment -> red.global.add.v2.f32
// (one LSU lane-op + one L2 op instead of two). Parity is uniform per thread.

#define GRID_R 128

__device__ __forceinline__ void red_add_f32(float* p, float v) {
    atomicAdd(p, v);  // return unused -> ptxas emits REDG (no-return)
}

__device__ __forceinline__ void red_add_v2_f32(float* p, float a, float b) {
    asm volatile("red.global.add.v2.f32 [%0], {%1, %2};"
                 :: "l"(p), "f"(a), "f"(b) : "memory");
}

__global__ __launch_bounds__(256)
void gridding_scatter_kernel(const float* __restrict__ pred,
                             const float* __restrict__ gt,
                             float* __restrict__ out,
                             int n_per_sample,
                             int total_points,
                             long long grid_per_cloud)
{
    int t = blockIdx.x * blockDim.x + threadIdx.x;
    if (t >= total_points) return;

    const float* __restrict__ pts = (blockIdx.y == 0) ? pred : gt;
    float* __restrict__ g = out + (long long)blockIdx.y * grid_per_cloud;

    float px = fmaf(pts[3 * t + 0], 128.0f, 64.0f);
    float py = fmaf(pts[3 * t + 1], 128.0f, 64.0f);
    float pz = fmaf(pts[3 * t + 2], 128.0f, 64.0f);

    float fx = floorf(px), fy = floorf(py), fz = floorf(pz);
    float dx = px - fx,   dy = py - fy,   dz = pz - fz;

    int ix = (int)fx, iy = (int)fy, iz = (int)fz;

    float wx0 = 1.0f - dx, wx1 = dx;
    float wy0 = 1.0f - dy, wy1 = dy;
    float wz0 = 1.0f - dz, wz1 = dz;

    float w00 = wx0 * wy0;
    float w01 = wx0 * wy1;
    float w10 = wx1 * wy0;
    float w11 = wx1 * wy1;

    int sample = t / n_per_sample;
    float* __restrict__ gb = g + (long long)sample * (GRID_R * GRID_R * GRID_R);

    bool interior = (ix >= 0) & (ix + 1 < GRID_R) &
                    (iy >= 0) & (iy + 1 < GRID_R) &
                    (iz >= 0) & (iz + 1 < GRID_R);

    if (interior) {
        int r00 = (ix * GRID_R + iy) * GRID_R + iz;            // (x0,y0,z0)
        int r01 = r00 + GRID_R;                                // (x0,y1,z0)
        int r10 = r00 + GRID_R * GRID_R;                       // (x1,y0,z0)
        int r11 = r10 + GRID_R;                                // (x1,y1,z0)

        if ((iz & 1) == 0) {
            // aligned 8B z-pairs -> vector reductions (4 ops, not 8)
            red_add_v2_f32(gb + r00, w00 * wz0, w00 * wz1);
            red_add_v2_f32(gb + r01, w01 * wz0, w01 * wz1);
            red_add_v2_f32(gb + r10, w10 * wz0, w10 * wz1);
            red_add_v2_f32(gb + r11, w11 * wz0, w11 * wz1);
        } else {
            red_add_f32(gb + r00,     w00 * wz0);
            red_add_f32(gb + r00 + 1, w00 * wz1);
            red_add_f32(gb + r01,     w01 * wz0);
            red_add_f32(gb + r01 + 1, w01 * wz1);
            red_add_f32(gb + r10,     w10 * wz0);
            red_add_f32(gb + r10 + 1, w10 * wz1);
            red_add_f32(gb + r11,     w11 * wz0);
            red_add_f32(gb + r11 + 1, w11 * wz1);
        }
    } else {
        // general clamped path (matches reference jnp.clip semantics)
        int ix0 = min(max(ix,     0), GRID_R - 1);
        int ix1 = min(max(ix + 1, 0), GRID_R - 1);
        int iy0 = min(max(iy,     0), GRID_R - 1);
        int iy1 = min(max(iy + 1, 0), GRID_R - 1);
        int iz0 = min(max(iz,     0), GRID_R - 1);
        int iz1 = min(max(iz + 1, 0), GRID_R - 1);
        int rx0 = ix0 * GRID_R * GRID_R, rx1 = ix1 * GRID_R * GRID_R;
        int ry0 = iy0 * GRID_R,          ry1 = iy1 * GRID_R;
        red_add_f32(gb + (rx0 + ry0 + iz0), w00 * wz0);
        red_add_f32(gb + (rx0 + ry0 + iz1), w00 * wz1);
        red_add_f32(gb + (rx0 + ry1 + iz0), w01 * wz0);
        red_add_f32(gb + (rx0 + ry1 + iz1), w01 * wz1);
        red_add_f32(gb + (rx1 + ry0 + iz0), w10 * wz0);
        red_add_f32(gb + (rx1 + ry0 + iz1), w10 * wz1);
        red_add_f32(gb + (rx1 + ry1 + iz0), w11 * wz0);
        red_add_f32(gb + (rx1 + ry1 + iz1), w11 * wz1);
    }
}

extern "C" void kernel_launch(void* const* d_in, const int* in_sizes, int n_in,
                              void* d_out, int out_size)
{
    const float* pred = (const float*)d_in[0];
    const float* gt   = (const float*)d_in[1];
    float* out = (float*)d_out;

    const int G = GRID_R * GRID_R * GRID_R;            // 2097152
    int b = out_size / (2 * G);                        // 8
    int total_points = in_sizes[0] / 3;                // b * n = 524288
    int n = total_points / b;                          // 65536
    long long grid_per_cloud = (long long)b * G;       // 16777216

    cudaMemsetAsync(d_out, 0, (size_t)out_size * sizeof(float));

    dim3 grid((total_points + 255) / 256, 2);
    gridding_scatter_kernel<<<grid, 256>>>(pred, gt, out, n, total_points,
                                           grid_per_cloud);
}

// round 3
// speedup vs baseline: 1.5354x; 1.3540x over previous
#include <cuda_runtime.h>
#include <cuda_bf16.h>
#include <cstdint>

// GriddingDistance: trilinear scatter of two point clouds into 128^3 voxel
// grids per batch sample. out = [pred_grid (b*G), gt_grid (b*G)] fp32.
//
// Round 3: phase the two clouds so each scatter's 64MB grid working set fits
// the 126MB L2 (atomics resolve in L2, no DRAM RMW thrash). The gt-half
// zero-fill is fused into the pred-scatter launch (independent block role).

#define GRID_R 128

__device__ __forceinline__ void red_add_f32(float* p, float v) {
    atomicAdd(p, v);  // return unused -> REDG (no-return reduction)
}

__device__ __forceinline__ void red_add_v2_f32(float* p, float a, float b) {
    asm volatile("red.global.add.v2.f32 [%0], {%1, %2};"
                 :: "l"(p), "f"(a), "f"(b) : "memory");
}

// Scatter one cloud into its grid half. Assumes pts has total_points points,
// grid base 'g' points at this cloud's first sample grid.
__device__ __forceinline__ void scatter_cloud(const float* __restrict__ pts,
                                              float* __restrict__ g,
                                              int n_per_sample,
                                              int total_points)
{
    int t = blockIdx.x * blockDim.x + threadIdx.x;
    if (t >= total_points) return;

    float px = fmaf(pts[3 * t + 0], 128.0f, 64.0f);
    float py = fmaf(pts[3 * t + 1], 128.0f, 64.0f);
    float pz = fmaf(pts[3 * t + 2], 128.0f, 64.0f);

    float fx = floorf(px), fy = floorf(py), fz = floorf(pz);
    float dx = px - fx,   dy = py - fy,   dz = pz - fz;

    int ix = (int)fx, iy = (int)fy, iz = (int)fz;

    float wx0 = 1.0f - dx, wx1 = dx;
    float wy0 = 1.0f - dy, wy1 = dy;
    float wz0 = 1.0f - dz, wz1 = dz;

    float w00 = wx0 * wy0;
    float w01 = wx0 * wy1;
    float w10 = wx1 * wy0;
    float w11 = wx1 * wy1;

    int sample = t / n_per_sample;
    float* __restrict__ gb = g + (long long)sample * (GRID_R * GRID_R * GRID_R);

    bool interior = (ix >= 0) & (ix + 1 < GRID_R) &
                    (iy >= 0) & (iy + 1 < GRID_R) &
                    (iz >= 0) & (iz + 1 < GRID_R);

    if (interior) {
        int r00 = (ix * GRID_R + iy) * GRID_R + iz;
        int r01 = r00 + GRID_R;
        int r10 = r00 + GRID_R * GRID_R;
        int r11 = r10 + GRID_R;

        if ((iz & 1) == 0) {
            red_add_v2_f32(gb + r00, w00 * wz0, w00 * wz1);
            red_add_v2_f32(gb + r01, w01 * wz0, w01 * wz1);
            red_add_v2_f32(gb + r10, w10 * wz0, w10 * wz1);
            red_add_v2_f32(gb + r11, w11 * wz0, w11 * wz1);
        } else {
            red_add_f32(gb + r00,     w00 * wz0);
            red_add_f32(gb + r00 + 1, w00 * wz1);
            red_add_f32(gb + r01,     w01 * wz0);
            red_add_f32(gb + r01 + 1, w01 * wz1);
            red_add_f32(gb + r10,     w10 * wz0);
            red_add_f32(gb + r10 + 1, w10 * wz1);
            red_add_f32(gb + r11,     w11 * wz0);
            red_add_f32(gb + r11 + 1, w11 * wz1);
        }
    } else {
        int ix0 = min(max(ix,     0), GRID_R - 1);
        int ix1 = min(max(ix + 1, 0), GRID_R - 1);
        int iy0 = min(max(iy,     0), GRID_R - 1);
        int iy1 = min(max(iy + 1, 0), GRID_R - 1);
        int iz0 = min(max(iz,     0), GRID_R - 1);
        int iz1 = min(max(iz + 1, 0), GRID_R - 1);
        int rx0 = ix0 * GRID_R * GRID_R, rx1 = ix1 * GRID_R * GRID_R;
        int ry0 = iy0 * GRID_R,          ry1 = iy1 * GRID_R;
        red_add_f32(gb + (rx0 + ry0 + iz0), w00 * wz0);
        red_add_f32(gb + (rx0 + ry0 + iz1), w00 * wz1);
        red_add_f32(gb + (rx0 + ry1 + iz0), w01 * wz0);
        red_add_f32(gb + (rx0 + ry1 + iz1), w01 * wz1);
        red_add_f32(gb + (rx1 + ry0 + iz0), w10 * wz0);
        red_add_f32(gb + (rx1 + ry0 + iz1), w10 * wz1);
        red_add_f32(gb + (rx1 + ry1 + iz0), w11 * wz0);
        red_add_f32(gb + (rx1 + ry1 + iz1), w11 * wz1);
    }
}

// Phase 2: blocks y==0 scatter pred; blocks y==1 zero the gt grid half.
__global__ __launch_bounds__(256)
void scatter_pred_zero_gt_kernel(const float* __restrict__ pred,
                                 float* __restrict__ out,
                                 int n_per_sample,
                                 int total_points,
                                 long long grid_per_cloud)
{
    if (blockIdx.y == 0) {
        scatter_cloud(pred, out, n_per_sample, total_points);
    } else {
        // zero gt half: grid_per_cloud floats starting at out + grid_per_cloud
        float4* __restrict__ z = (float4*)(out + grid_per_cloud);
        long long n4 = grid_per_cloud >> 2;                 // float4 count
        long long nthreads = (long long)gridDim.x * blockDim.x;
        long long t = (long long)blockIdx.x * blockDim.x + threadIdx.x;
        float4 zero = make_float4(0.f, 0.f, 0.f, 0.f);
        for (long long i = t; i < n4; i += nthreads)
            z[i] = zero;
    }
}

__global__ __launch_bounds__(256)
void scatter_gt_kernel(const float* __restrict__ gt,
                       float* __restrict__ out,
                       int n_per_sample,
                       int total_points,
                       long long grid_per_cloud)
{
    scatter_cloud(gt, out + grid_per_cloud, n_per_sample, total_points);
}

extern "C" void kernel_launch(void* const* d_in, const int* in_sizes, int n_in,
                              void* d_out, int out_size)
{
    const float* pred = (const float*)d_in[0];
    const float* gt   = (const float*)d_in[1];
    float* out = (float*)d_out;

    const int G = GRID_R * GRID_R * GRID_R;            // 2097152
    int b = out_size / (2 * G);                        // 8
    int total_points = in_sizes[0] / 3;                // b * n = 524288
    int n = total_points / b;                          // 65536
    long long grid_per_cloud = (long long)b * G;       // 16777216 floats

    // Phase 1: zero pred half only (lands in L2, stays resident for phase 2)
    cudaMemsetAsync(d_out, 0, (size_t)grid_per_cloud * sizeof(float));

    int nblk = (total_points + 255) / 256;             // 2048

    // Phase 2: scatter pred (L2-resident grid) + zero gt half concurrently
    dim3 grid2(nblk, 2);
    scatter_pred_zero_gt_kernel<<<grid2, 256>>>(pred, out, n, total_points,
                                                grid_per_cloud);

    // Phase 3: scatter gt (its grid now L2-resident from phase 2 zeroing)
    scatter_gt_kernel<<<nblk, 256>>>(gt, out, n, total_points, grid_per_cloud);
}